// round 9
// baseline (speedup 1.0000x reference)
#include <cuda_runtime.h>

#define BB   512
#define NN   64
#define KNBR 16
#define NPTS  (BB*NN)      /* 32768  */
#define NEDGE (BB*NN*KNBR) /* 524288 */
#define EPSV 1e-5f

/* ---------------- scratch layout (floats, one big device array) ---------------- */
#define OFF_H0   0UL
#define OFF_H1   2097152UL
#define OFF_H2   4194304UL
#define OFF_H3   8388608UL
#define OFF_P    16777216UL
#define OFF_Q    25165824UL
#define OFF_WA   33554432UL
#define OFF_WB   33619968UL
#define OFF_POOL 33685504UL
#define OFF_C1   34144256UL
#define OFF_Z1   34406400UL
#define OFF_C2   34668544UL
#define OFF_Z2   34799616UL
#define OFF_HPRE 34930688UL
#define TOTAL_SCRATCH 169148416UL   /* ~677 MB */

__device__ float  g_scratch[TOTAL_SCRATCH];
__device__ int    g_idx[NEDGE];
__device__ double g_sum[9*512];
__device__ double g_ssq[9*512];
__device__ float  g_scale[9*512];
__device__ float  g_shift[9*512];

__device__ __forceinline__ float lrelu_f(float v) { return v > 0.f ? v : 0.2f*v; }

/* ------------------------------ small helpers ------------------------------ */
__global__ void k_zero_stats() {
    int i = blockIdx.x*blockDim.x + threadIdx.x;
    if (i < 9*512) { g_sum[i] = 0.0; g_ssq[i] = 0.0; }
}

/* h0pre = x @ w_in  (K = 6) */
__global__ void k_ingemm(const float* __restrict__ x, const float* __restrict__ w,
                         size_t ooff) {
    int i = blockIdx.x*blockDim.x + threadIdx.x;
    if (i >= NPTS*64) return;
    int r = i >> 6, c = i & 63;
    float s = 0.f;
#pragma unroll
    for (int k = 0; k < 6; k++) s += x[r*6 + k] * w[k*64 + c];
    g_scratch[ooff + i] = s;
}

/* per-channel sum / sumsq of a dense (M, C) scratch matrix */
__global__ void k_colstats(size_t aoff, int M, int C, int slot) {
    int c = blockIdx.x*64 + threadIdx.x;
    if (c >= C) return;
    const float* A = g_scratch + aoff;
    float s = 0.f, q = 0.f;
    for (int r = blockIdx.y; r < M; r += gridDim.y) {
        float v = A[(size_t)r*C + c]; s += v; q += v*v;
    }
    atomicAdd(&g_sum[slot*512 + c], (double)s);
    atomicAdd(&g_ssq[slot*512 + c], (double)q);
}

__global__ void k_finalize(int slot, const float* __restrict__ g,
                           const float* __restrict__ b, double invM, int C) {
    int c = blockIdx.x*blockDim.x + threadIdx.x;
    if (c >= C) return;
    double m = g_sum[slot*512 + c]*invM;
    double v = g_ssq[slot*512 + c]*invM - m*m;
    float rs = rsqrtf((float)v + EPSV);
    float sc = g[c]*rs;
    g_scale[slot*512 + c] = sc;
    g_shift[slot*512 + c] = b[c] - (float)m*sc;
}

__global__ void k_bnlrelu(size_t aoff, size_t ooff, int total, int C, int slot) {
    int i = blockIdx.x*blockDim.x + threadIdx.x;
    if (i >= total) return;
    int c = i % C;
    g_scratch[ooff + i] =
        lrelu_f(g_scratch[aoff + i]*g_scale[slot*512 + c] + g_shift[slot*512 + c]);
}

/* ---------------------------------- knn ------------------------------------ */
/* one block per cloud; channel-chunked 64x64 Gram matrix; 256 threads.
 * Selection emulates jax.lax.top_k(-d, K+1)[:,:,1:] EXACTLY:
 *   - self included in the candidate set with d=0 (exact),
 *   - stable top-(K+1): ties broken by ascending index,
 *   - first slot dropped.
 * This matters for degenerate duplicate rows (all-zero features from
 * scatter-max of never-referenced points): all pairwise distances are exact
 * 0 and the reference then keeps self / drops the lowest-index duplicate.  */
__global__ void k_knn(size_t xoff, int C) {
    __shared__ float xs[64][65];
    __shared__ float D [64][65];
    __shared__ float sq[64];
    int b = blockIdx.x, tid = threadIdx.x;
    const float* X = g_scratch + xoff;
    for (int i = tid; i < 64*64; i += 256) D[i>>6][i&63] = 0.f;
    if (tid < 64) sq[tid] = 0.f;
    for (int c0 = 0; c0 < C; c0 += 64) {
        __syncthreads();
        for (int i = tid; i < 64*64; i += 256)
            xs[i>>6][i&63] = X[(size_t)(b*64 + (i>>6))*C + c0 + (i&63)];
        __syncthreads();
        int n = tid >> 2, mb = (tid & 3) << 4;
        float acc[16];
#pragma unroll
        for (int mm = 0; mm < 16; mm++) acc[mm] = 0.f;
        for (int c = 0; c < 64; c++) {
            float xv = xs[n][c];
#pragma unroll
            for (int mm = 0; mm < 16; mm++) acc[mm] += xv * xs[mb+mm][c];
        }
#pragma unroll
        for (int mm = 0; mm < 16; mm++) D[n][mb+mm] += acc[mm];
        if (tid < 64) {
            float s = 0.f;
            for (int c = 0; c < 64; c++) { float v = xs[tid][c]; s += v*v; }
            sq[tid] += s;
        }
    }
    __syncthreads();
    if (tid < 64) {
        int n = tid;
        float bd[KNBR+1]; int bi[KNBR+1];
#pragma unroll
        for (int q = 0; q <= KNBR; q++) { bd[q] = 3.402823466e38f; bi[q] = 0; }
        float sn = sq[n];
        for (int m = 0; m < 64; m++) {
            float d = (sn - 2.f*D[n][m]) + sq[m];
            if (m == n) d = 0.f;                    /* self: exact zero, like ref */
            if (d < bd[KNBR]) {                     /* strict: stable on ties */
                int p = KNBR;
                while (p > 0 && d < bd[p-1]) { bd[p]=bd[p-1]; bi[p]=bi[p-1]; p--; }
                bd[p] = d; bi[p] = m;
            }
        }
        for (int q = 1; q <= KNBR; q++) g_idx[b*1024 + n*16 + (q-1)] = bi[q];
    }
}

/* Wa = w1_top - w1_bot (neighbor), Wb = w1_bot (center) */
__global__ void k_wab(const float* __restrict__ w1, int Cin, int Cmid) {
    int i = blockIdx.x*blockDim.x + threadIdx.x;
    if (i >= Cin*Cmid) return;
    float wb = w1[Cin*Cmid + i];
    g_scratch[OFF_WA + i] = w1[i] - wb;
    g_scratch[OFF_WB + i] = wb;
}

/* --------------------- generic tiled fp32 GEMM (scratch) -------------------- */
/* C(M,N) = A(M,K) @ W(K,N); M%64==0, K%16==0, N%64==0; 256 thr, 4x4 microtile */
__global__ void k_gemm(size_t aoff, const float* __restrict__ Wext, size_t woff,
                       size_t coff, int M, int K, int N) {
    __shared__ float As[16][68];
    __shared__ float Ws[16][68];
    const float* A = g_scratch + aoff;
    const float* W = Wext ? Wext : (g_scratch + woff);
    float* Co = g_scratch + coff;
    int tid = threadIdx.x;
    int cb = blockIdx.x*64, rb = blockIdx.y*64;
    int tx = tid & 15, ty = tid >> 4;
    float acc[4][4];
#pragma unroll
    for (int i = 0; i < 4; i++)
#pragma unroll
        for (int j = 0; j < 4; j++) acc[i][j] = 0.f;
    for (int k0 = 0; k0 < K; k0 += 16) {
        for (int i = tid; i < 64*16; i += 256) {
            int r = i >> 4, c = i & 15;
            As[c][r] = A[(size_t)(rb+r)*K + k0 + c];
        }
        for (int i = tid; i < 16*64; i += 256) {
            int r = i >> 6, c = i & 63;
            Ws[r][c] = W[(size_t)(k0+r)*N + cb + c];
        }
        __syncthreads();
#pragma unroll
        for (int k = 0; k < 16; k++) {
            float a[4], w4[4];
#pragma unroll
            for (int i = 0; i < 4; i++) a[i]  = As[k][ty*4+i];
#pragma unroll
            for (int j = 0; j < 4; j++) w4[j] = Ws[k][tx*4+j];
#pragma unroll
            for (int i = 0; i < 4; i++)
#pragma unroll
                for (int j = 0; j < 4; j++) acc[i][j] += a[i]*w4[j];
        }
        __syncthreads();
    }
    for (int i = 0; i < 4; i++)
        for (int j = 0; j < 4; j++)
            Co[(size_t)(rb+ty*4+i)*N + cb + tx*4 + j] = acc[i][j];
}

/* stats of virtual h1pre[edge] = P[j] + Q[n]; one block per cloud, Cmid thr */
__global__ void k_edge_stats(int Cmid, int slot) {
    __shared__ int sidx[1024];
    int b = blockIdx.x, c = threadIdx.x;
    for (int i = c; i < 1024; i += blockDim.x) sidx[i] = g_idx[b*1024 + i];
    __syncthreads();
    const float* Pb = g_scratch + OFF_P + (size_t)b*64*Cmid;
    const float* Qb = g_scratch + OFF_Q + (size_t)b*64*Cmid;
    float s = 0.f, q = 0.f;
    for (int n = 0; n < 64; n++) {
        float qv = Qb[(size_t)n*Cmid + c];
        for (int k = 0; k < 16; k++) {
            float v = Pb[(size_t)sidx[n*16+k]*Cmid + c] + qv;
            s += v; q += v*v;
        }
    }
    atomicAdd(&g_sum[slot*512 + c], (double)s);
    atomicAdd(&g_ssq[slot*512 + c], (double)q);
}

/* ---------- fused gather + BN + lrelu + GEMM2 + stats epilogue -------------- */
/* 128 edge rows x 64 out cols per block, 128 threads, 8x8 microtile           */
__global__ void __launch_bounds__(128)
k_gemm_edge(const float* __restrict__ W2, int Cmid, int Cout, int slotA, int slotB) {
    __shared__ float Ps[64][33];
    __shared__ float Qs[8][33];
    __shared__ float Wsh[32][68];
    __shared__ float Xs[32][132];
    __shared__ float s_sc[32], s_sh[32];
    __shared__ int   sidx[128];
    __shared__ float red_s[64], red_q[64];
    int tid = threadIdx.x;
    int cb = blockIdx.x*64;
    int rowBase = blockIdx.y*128;
    int b = rowBase >> 10;
    int pBase = (rowBase >> 4) & 63;
    sidx[tid] = g_idx[rowBase + tid];
    if (tid < 64) { red_s[tid] = 0.f; red_q[tid] = 0.f; }
    float acc[8][8];
#pragma unroll
    for (int i = 0; i < 8; i++)
#pragma unroll
        for (int j = 0; j < 8; j++) acc[i][j] = 0.f;
    int tx = tid & 7, ty = tid >> 3;
    const float* scp = g_scale + slotA*512;
    const float* shp = g_shift + slotA*512;
    for (int k0 = 0; k0 < Cmid; k0 += 32) {
        if (tid < 32) { s_sc[tid] = scp[k0+tid]; s_sh[tid] = shp[k0+tid]; }
        const float* Pb = g_scratch + OFF_P + (size_t)(b*64)*Cmid + k0;
        for (int i = tid; i < 64*32; i += 128)
            Ps[i>>5][i&31] = Pb[(size_t)(i>>5)*Cmid + (i&31)];
        const float* Qb = g_scratch + OFF_Q + (size_t)(b*64 + pBase)*Cmid + k0;
        for (int i = tid; i < 8*32; i += 128)
            Qs[i>>5][i&31] = Qb[(size_t)(i>>5)*Cmid + (i&31)];
        const float* Wp = W2 + (size_t)k0*Cout + cb;
        for (int i = tid; i < 32*64; i += 128)
            Wsh[i>>6][i&63] = Wp[(size_t)(i>>6)*Cout + (i&63)];
        __syncthreads();
        {
            int j = sidx[tid], p = tid >> 4;
#pragma unroll
            for (int k = 0; k < 32; k++) {
                float v = Ps[j][k] + Qs[p][k];
                v = v*s_sc[k] + s_sh[k];
                Xs[k][tid] = v > 0.f ? v : 0.2f*v;
            }
        }
        __syncthreads();
#pragma unroll 4
        for (int k = 0; k < 32; k++) {
            float4 a0 = *(const float4*)&Xs[k][ty*8];
            float4 a1 = *(const float4*)&Xs[k][ty*8+4];
            float4 b0 = *(const float4*)&Wsh[k][tx*8];
            float4 b1 = *(const float4*)&Wsh[k][tx*8+4];
            float av[8] = {a0.x,a0.y,a0.z,a0.w,a1.x,a1.y,a1.z,a1.w};
            float bv[8] = {b0.x,b0.y,b0.z,b0.w,b1.x,b1.y,b1.z,b1.w};
#pragma unroll
            for (int i = 0; i < 8; i++)
#pragma unroll
                for (int j = 0; j < 8; j++) acc[i][j] += av[i]*bv[j];
        }
        __syncthreads();
    }
    float cs[8], cq[8];
#pragma unroll
    for (int j = 0; j < 8; j++) { cs[j] = 0.f; cq[j] = 0.f; }
    float* H = g_scratch + OFF_HPRE + (size_t)rowBase*Cout + cb;
#pragma unroll
    for (int i = 0; i < 8; i++) {
        int r = ty*8 + i;
        float4 v0 = make_float4(acc[i][0],acc[i][1],acc[i][2],acc[i][3]);
        float4 v1 = make_float4(acc[i][4],acc[i][5],acc[i][6],acc[i][7]);
        *(float4*)&H[(size_t)r*Cout + tx*8]     = v0;
        *(float4*)&H[(size_t)r*Cout + tx*8 + 4] = v1;
#pragma unroll
        for (int j = 0; j < 8; j++) { cs[j] += acc[i][j]; cq[j] += acc[i][j]*acc[i][j]; }
    }
#pragma unroll
    for (int j = 0; j < 8; j++) {
        atomicAdd(&red_s[tx*8+j], cs[j]);
        atomicAdd(&red_q[tx*8+j], cq[j]);
    }
    __syncthreads();
    if (tid < 64) {
        atomicAdd(&g_sum[slotB*512 + cb + tid], (double)red_s[tid]);
        atomicAdd(&g_ssq[slotB*512 + cb + tid], (double)red_q[tid]);
    }
}

/* ------------- BN + lrelu + scatter-max into output points ----------------- */
/* grid (512, Cout/64), 256 threads, 64 channels per block                     */
__global__ void k_scatter(size_t outoff, int Cout, int slot) {
    __shared__ float facc[64*64];
    __shared__ int   sidx[1024];
    __shared__ float s_sc[64], s_sh[64];
    int b = blockIdx.x, cb = blockIdx.y*64, tid = threadIdx.x;
    const float NEGINF = __int_as_float(0xff800000);
    for (int i = tid; i < 1024; i += 256) sidx[i] = g_idx[b*1024 + i];
    for (int i = tid; i < 64*64; i += 256) facc[i] = NEGINF;
    if (tid < 64) {
        s_sc[tid] = g_scale[slot*512 + cb + tid];
        s_sh[tid] = g_shift[slot*512 + cb + tid];
    }
    __syncthreads();
    const float* Hb = g_scratch + OFF_HPRE + (size_t)b*1024*Cout + cb;
    for (int i = tid; i < 1024*64; i += 256) {
        int e = i >> 6, c = i & 63;
        float v = Hb[(size_t)e*Cout + c];
        v = v*s_sc[c] + s_sh[c];
        v = v > 0.f ? v : 0.2f*v;
        float* addr = &facc[(sidx[e] << 6) + c];
        if (v >= 0.f) atomicMax((int*)addr, __float_as_int(v));
        else          atomicMin((unsigned int*)addr, __float_as_uint(v));
    }
    __syncthreads();
    float* ob = g_scratch + outoff + (size_t)b*64*Cout + cb;
    for (int i = tid; i < 64*64; i += 256) {
        int n = i >> 6, c = i & 63;
        float v = facc[i];
        if (v == NEGINF) v = 0.f;
        ob[(size_t)n*Cout + c] = v;
    }
}

/* ----------------------------- global pooling ------------------------------ */
__global__ void k_pool() {
    int b = blockIdx.x, c = threadIdx.x;          /* 448 threads */
    const float* src; int C, cc;
    if (c < 64)       { C = 64;  cc = c;       src = g_scratch + OFF_H1; }
    else if (c < 192) { C = 128; cc = c - 64;  src = g_scratch + OFF_H2; }
    else              { C = 256; cc = c - 192; src = g_scratch + OFF_H3; }
    float s = 0.f, mx = -3.402823466e38f;
    for (int n = 0; n < 64; n++) {
        float v = src[(size_t)(b*64 + n)*C + cc];
        s += v; mx = fmaxf(mx, v);
    }
    g_scratch[OFF_POOL + (size_t)b*896 + c]       = s * (1.f/64.f);
    g_scratch[OFF_POOL + (size_t)b*896 + 448 + c] = mx;
}

/* ------------------------------ final linear ------------------------------- */
__global__ void k_final(const float* __restrict__ wc3, const float* __restrict__ bc3,
                        float* __restrict__ out) {
    int i = blockIdx.x*blockDim.x + threadIdx.x;
    if (i >= 1024) return;
    int r = i >> 1, c = i & 1;
    const float* z = g_scratch + OFF_Z2 + (size_t)r*256;
    float s = 0.f;
    for (int k = 0; k < 256; k++) s += z[k] * wc3[k*2 + c];
    out[i] = s + bc3[c];
}

/* --------------------------------- driver ---------------------------------- */
static void run_layer(size_t xoff, int Cin, const float* w1, int Cmid,
                      const float* w2, int Cout,
                      const float* g1, const float* b1,
                      const float* g2, const float* b2,
                      int slotA, int slotB, size_t outoff) {
    k_knn<<<512, 256>>>(xoff, Cin);
    k_wab<<<(Cin*Cmid + 255)/256, 256>>>(w1, Cin, Cmid);
    k_gemm<<<dim3(Cmid/64, NPTS/64), 256>>>(xoff, nullptr, OFF_WA, OFF_P, NPTS, Cin, Cmid);
    k_gemm<<<dim3(Cmid/64, NPTS/64), 256>>>(xoff, nullptr, OFF_WB, OFF_Q, NPTS, Cin, Cmid);
    k_edge_stats<<<512, Cmid>>>(Cmid, slotA);
    k_finalize<<<(Cmid+63)/64, 64>>>(slotA, g1, b1, 1.0/NEDGE, Cmid);
    k_gemm_edge<<<dim3(Cout/64, NEDGE/128), 128>>>(w2, Cmid, Cout, slotA, slotB);
    k_finalize<<<(Cout+63)/64, 64>>>(slotB, g2, b2, 1.0/NEDGE, Cout);
    k_scatter<<<dim3(512, Cout/64), 256>>>(outoff, Cout, slotB);
}

extern "C" void kernel_launch(void* const* d_in, const int* in_sizes, int n_in,
                              void* d_out, int out_size) {
    const float* x    = (const float*)d_in[0];
    const float* w_in = (const float*)d_in[2];
    const float* g_in = (const float*)d_in[3];
    const float* b_in = (const float*)d_in[4];
    const float* w1a  = (const float*)d_in[5];
    const float* g1a  = (const float*)d_in[6];
    const float* b1a  = (const float*)d_in[7];
    const float* w1b  = (const float*)d_in[8];
    const float* g1b  = (const float*)d_in[9];
    const float* b1b  = (const float*)d_in[10];
    const float* w2a  = (const float*)d_in[11];
    const float* g2a  = (const float*)d_in[12];
    const float* b2a  = (const float*)d_in[13];
    const float* w2b  = (const float*)d_in[14];
    const float* g2b  = (const float*)d_in[15];
    const float* b2b  = (const float*)d_in[16];
    const float* w3a  = (const float*)d_in[17];
    const float* g3a  = (const float*)d_in[18];
    const float* b3a  = (const float*)d_in[19];
    const float* w3b  = (const float*)d_in[20];
    const float* g3b  = (const float*)d_in[21];
    const float* b3b  = (const float*)d_in[22];
    const float* wc1  = (const float*)d_in[23];
    const float* gc1  = (const float*)d_in[24];
    const float* bc1  = (const float*)d_in[25];
    const float* wc2  = (const float*)d_in[26];
    const float* gc2  = (const float*)d_in[27];
    const float* bc2  = (const float*)d_in[28];
    const float* wc3  = (const float*)d_in[29];
    const float* bc3  = (const float*)d_in[30];

    k_zero_stats<<<18, 256>>>();

    /* input MLP: h0 = lrelu(bn(x @ w_in)) */
    k_ingemm<<<(NPTS*64 + 255)/256, 256>>>(x, w_in, OFF_P);
    k_colstats<<<dim3(1, 64), 64>>>(OFF_P, NPTS, 64, 0);
    k_finalize<<<1, 64>>>(0, g_in, b_in, 1.0/NPTS, 64);
    k_bnlrelu<<<(NPTS*64 + 255)/256, 256>>>(OFF_P, OFF_H0, NPTS*64, 64, 0);

    run_layer(OFF_H0, 64,  w1a, 64,  w1b, 64,  g1a, b1a, g1b, b1b, 1, 2, OFF_H1);
    run_layer(OFF_H1, 64,  w2a, 128, w2b, 128, g2a, b2a, g2b, b2b, 3, 4, OFF_H2);
    run_layer(OFF_H2, 128, w3a, 256, w3b, 256, g3a, b3a, g3b, b3b, 5, 6, OFF_H3);

    k_pool<<<512, 448>>>();

    /* classifier */
    k_gemm<<<dim3(8, 8), 256>>>(OFF_POOL, wc1, 0, OFF_C1, 512, 896, 512);
    k_colstats<<<dim3(8, 64), 64>>>(OFF_C1, 512, 512, 7);
    k_finalize<<<8, 64>>>(7, gc1, bc1, 1.0/512, 512);
    k_bnlrelu<<<(512*512 + 255)/256, 256>>>(OFF_C1, OFF_Z1, 512*512, 512, 7);

    k_gemm<<<dim3(4, 8), 256>>>(OFF_Z1, wc2, 0, OFF_C2, 512, 512, 256);
    k_colstats<<<dim3(4, 64), 64>>>(OFF_C2, 512, 256, 8);
    k_finalize<<<4, 64>>>(8, gc2, bc2, 1.0/512, 256);
    k_bnlrelu<<<(512*256 + 255)/256, 256>>>(OFF_C2, OFF_Z2, 512*256, 256, 8);

    k_final<<<4, 256>>>(wc3, bc3, (float*)d_out);
}